// round 3
// baseline (speedup 1.0000x reference)
#include <cuda_runtime.h>
#include <cuda_bf16.h>
#include <cstdint>

// LatticeGaussian: out[i,c] = sum_j exp(-0.5*||ref_i-ref_j||^2) * U[j,c] - U[i,c]
// N=8192, C=16, D=5.  fp32 brute force, fma-pipe bound, f32x2-packed.
//  - grid (N/TI, SPLITS): block owns TI=256 rows i, j-chunk of TJ=512.
//  - exponent arg for 2 j's computed with one packed chain:
//      arg_j = sqi_s + base_j + sum_d ri[d]*(log2e*rj[d]),
//      sqi_s = -0.5*log2e*|ri|^2, base_j = -0.5*log2e*|rj|^2
//  - 16-ch MAC: 8x fma.rn.f32x2 per j into 16 packed accumulators (8 per
//    j-parity), merged once at the end. No d2 clamp (error ~1e-7).
//  - deterministic: per-split partials, reduce kernel folds -U.

#define NN 8192
#define CC 16
#define DD 5
#define TI 256
#define TJ 512
#define JP (TJ / 2)
#define SPLITS (NN / TJ)

#define LOG2E 1.4426950408889634f
#define NHALF_LOG2E (-0.7213475204444817f)

__device__ float g_partial[SPLITS][NN][CC];   // 8 MB static scratch

__device__ __forceinline__ void ffma2(unsigned long long& d,
                                      unsigned long long a,
                                      unsigned long long b) {
    asm volatile("fma.rn.f32x2 %0, %1, %2, %0;" : "+l"(d) : "l"(a), "l"(b));
}
__device__ __forceinline__ unsigned long long add2(unsigned long long a,
                                                   unsigned long long b) {
    unsigned long long r;
    asm("add.rn.f32x2 %0, %1, %2;" : "=l"(r) : "l"(a), "l"(b));
    return r;
}
__device__ __forceinline__ unsigned long long bcast2(float x) {
    unsigned long long r;
    asm("mov.b64 %0, {%1, %1};" : "=l"(r) : "f"(x));
    return r;
}
__device__ __forceinline__ float ex2_approx(float x) {
    float r;
    asm("ex2.approx.f32 %0, %1;" : "=f"(r) : "f"(x));
    return r;
}

__global__ void __launch_bounds__(TI, 2)
lg_compute(const float* __restrict__ U, const float* __restrict__ ref) {
    __shared__ float4 Us[TJ * 4];   // U rows, 64B each            (32 KB)
    __shared__ float4 Rp[JP * 3];   // packed scaled ref pairs     (12 KB)

    const int tid = threadIdx.x;
    const int i   = blockIdx.x * TI + tid;
    const int j0  = blockIdx.y * TJ;

    const float4* Ug = reinterpret_cast<const float4*>(U + (size_t)j0 * CC);
    #pragma unroll
    for (int k = tid; k < TJ * 4; k += TI) Us[k] = Ug[k];

    {   // one ref pair per thread (JP == TI)
        const int jp = tid;
        const float* ra = ref + (size_t)(j0 + 2 * jp) * DD;
        const float* rb = ra + DD;
        float a0=ra[0],a1=ra[1],a2=ra[2],a3=ra[3],a4=ra[4];
        float b0=rb[0],b1=rb[1],b2=rb[2],b3=rb[3],b4=rb[4];
        float sa = fmaf(a0,a0,fmaf(a1,a1,fmaf(a2,a2,fmaf(a3,a3,a4*a4))));
        float sb = fmaf(b0,b0,fmaf(b1,b1,fmaf(b2,b2,fmaf(b3,b3,b4*b4))));
        Rp[jp*3+0] = make_float4(a0*LOG2E, b0*LOG2E, a1*LOG2E, b1*LOG2E);
        Rp[jp*3+1] = make_float4(a2*LOG2E, b2*LOG2E, a3*LOG2E, b3*LOG2E);
        Rp[jp*3+2] = make_float4(a4*LOG2E, b4*LOG2E,
                                 sa*NHALF_LOG2E, sb*NHALF_LOG2E);
    }
    __syncthreads();

    const float r0 = ref[(size_t)i*DD+0], r1 = ref[(size_t)i*DD+1];
    const float r2 = ref[(size_t)i*DD+2], r3 = ref[(size_t)i*DD+3];
    const float r4 = ref[(size_t)i*DD+4];
    const float sqi = fmaf(r0,r0,fmaf(r1,r1,fmaf(r2,r2,fmaf(r3,r3,r4*r4))));
    const unsigned long long ri2[DD] = {
        bcast2(r0), bcast2(r1), bcast2(r2), bcast2(r3), bcast2(r4)
    };
    const unsigned long long sqi2 = bcast2(sqi * NHALF_LOG2E);

    unsigned long long acc[16];     // [0..7]: even j rows, [8..15]: odd j rows
    #pragma unroll
    for (int k = 0; k < 16; k++) acc[k] = 0ull;

    #pragma unroll 2
    for (int jp = 0; jp < JP; jp++) {
        const float4 p0 = Rp[jp*3+0];
        const float4 p1 = Rp[jp*3+1];
        const float4 p2 = Rp[jp*3+2];
        const unsigned long long* q0 = (const unsigned long long*)&p0;
        const unsigned long long* q1 = (const unsigned long long*)&p1;
        const unsigned long long* q2 = (const unsigned long long*)&p2;

        unsigned long long arg2 = add2(sqi2, q2[1]);
        ffma2(arg2, ri2[0], q0[0]);
        ffma2(arg2, ri2[1], q0[1]);
        ffma2(arg2, ri2[2], q1[0]);
        ffma2(arg2, ri2[3], q1[1]);
        ffma2(arg2, ri2[4], q2[0]);

        float e0, e1;
        asm("mov.b64 {%0, %1}, %2;" : "=f"(e0), "=f"(e1) : "l"(arg2));
        const unsigned long long w0 = bcast2(ex2_approx(e0));
        const unsigned long long w1 = bcast2(ex2_approx(e1));

        const ulonglong2* ua = (const ulonglong2*)&Us[(2*jp    ) * 4];
        const ulonglong2* ub = (const ulonglong2*)&Us[(2*jp + 1) * 4];
        ulonglong2 a0v = ua[0], a1v = ua[1];   // row 2jp:   pairs 0..3
        ulonglong2 a2v = ua[2], a3v = ua[3];   //            pairs 4..7
        ulonglong2 b0v = ub[0], b1v = ub[1];   // row 2jp+1
        ulonglong2 b2v = ub[2], b3v = ub[3];
        ffma2(acc[0],  w0, a0v.x); ffma2(acc[1],  w0, a0v.y);
        ffma2(acc[2],  w0, a1v.x); ffma2(acc[3],  w0, a1v.y);
        ffma2(acc[4],  w0, a2v.x); ffma2(acc[5],  w0, a2v.y);
        ffma2(acc[6],  w0, a3v.x); ffma2(acc[7],  w0, a3v.y);
        ffma2(acc[8],  w1, b0v.x); ffma2(acc[9],  w1, b0v.y);
        ffma2(acc[10], w1, b1v.x); ffma2(acc[11], w1, b1v.y);
        ffma2(acc[12], w1, b2v.x); ffma2(acc[13], w1, b2v.y);
        ffma2(acc[14], w1, b3v.x); ffma2(acc[15], w1, b3v.y);
    }

    unsigned long long* P =
        reinterpret_cast<unsigned long long*>(&g_partial[blockIdx.y][i][0]);
    #pragma unroll
    for (int k = 0; k < 8; k++) P[k] = add2(acc[k], acc[k + 8]);
}

__global__ void __launch_bounds__(256)
lg_reduce(const float* __restrict__ U, float* __restrict__ out) {
    const int idx = blockIdx.x * 256 + threadIdx.x;
    const float* base = reinterpret_cast<const float*>(g_partial);
    float s = -U[idx];
    #pragma unroll
    for (int p = 0; p < SPLITS; p++) s += base[(size_t)p * NN * CC + idx];
    out[idx] = s;
}

extern "C" void kernel_launch(void* const* d_in, const int* in_sizes, int n_in,
                              void* d_out, int out_size) {
    const float* U   = (const float*)d_in[0];   // [8192,16]
    const float* ref = (const float*)d_in[1];   // [8192,5]
    float* out = (float*)d_out;                 // [8192,16]

    dim3 grid(NN / TI, SPLITS);
    lg_compute<<<grid, TI>>>(U, ref);
    lg_reduce<<<(NN * CC) / 256, 256>>>(U, out);
}

// round 6
// speedup vs baseline: 1.2776x; 1.2776x over previous
#include <cuda_runtime.h>
#include <cuda_bf16.h>
#include <cstdint>

// LatticeGaussian: out[i,c] = sum_j exp(-0.5*||ref_i-ref_j||^2) * U[j,c] - U[i,c]
// N=8192, C=16, D=5.  fp32 brute force, fma-pipe bound, f32x2-packed.
//
// 2 i-rows per thread (2 independent dep chains, double FMA per LDS byte),
// 8 packed accumulators per i-row, occupancy 4 blocks/SM (128-reg budget,
// guaranteed no inner-loop spill), vectorized reduce.
//
//   arg_j = nh*(|ri|^2+|rj|^2) + log2e*(ri.rj),  w = ex2(arg_j)
// staged per j-pair as packed f32x2 lanes. No d2 clamp (error ~1e-7 in w).

#define NN 8192
#define CC 16
#define DD 5
#define TI 128            // threads per block; block covers 2*TI = 256 i-rows
#define TJ 512
#define JP (TJ / 2)       // 256 j-pairs
#define SPLITS (NN / TJ)  // 16

#define LOG2E 1.4426950408889634f
#define NHALF_LOG2E (-0.7213475204444817f)

__device__ float g_partial[SPLITS][NN][CC];   // 8 MB static scratch

__device__ __forceinline__ void ffma2(unsigned long long& d,
                                      unsigned long long a,
                                      unsigned long long b) {
    asm volatile("fma.rn.f32x2 %0, %1, %2, %0;" : "+l"(d) : "l"(a), "l"(b));
}
__device__ __forceinline__ unsigned long long add2(unsigned long long a,
                                                   unsigned long long b) {
    unsigned long long r;
    asm("add.rn.f32x2 %0, %1, %2;" : "=l"(r) : "l"(a), "l"(b));
    return r;
}
__device__ __forceinline__ unsigned long long bcast2(float x) {
    unsigned long long r;
    asm("mov.b64 %0, {%1, %1};" : "=l"(r) : "f"(x));
    return r;
}
__device__ __forceinline__ float ex2_approx(float x) {
    float r;
    asm("ex2.approx.f32 %0, %1;" : "=f"(r) : "f"(x));
    return r;
}

__global__ void __launch_bounds__(TI, 4)
lg_compute(const float* __restrict__ U, const float* __restrict__ ref) {
    __shared__ float4 Us[TJ * 4];   // U rows of j-chunk, 64B each   (32 KB)
    __shared__ float4 Rp[JP * 3];   // packed scaled ref pairs       (12 KB)

    const int tid = threadIdx.x;
    const int iA  = blockIdx.x * (2 * TI) + tid;        // first i-row
    const int iB  = iA + TI;                            // second i-row
    const int j0  = blockIdx.y * TJ;

    // Stage U rows of the j-chunk.
    const float4* Ug = reinterpret_cast<const float4*>(U + (size_t)j0 * CC);
    #pragma unroll
    for (int k = tid; k < TJ * 4; k += TI) Us[k] = Ug[k];

    // Stage packed scaled ref pairs: 2 pairs per thread (JP == 2*TI).
    #pragma unroll
    for (int jp = tid; jp < JP; jp += TI) {
        const float* ra = ref + (size_t)(j0 + 2 * jp) * DD;
        const float* rb = ra + DD;
        float a0=ra[0],a1=ra[1],a2=ra[2],a3=ra[3],a4=ra[4];
        float b0=rb[0],b1=rb[1],b2=rb[2],b3=rb[3],b4=rb[4];
        float sa = fmaf(a0,a0,fmaf(a1,a1,fmaf(a2,a2,fmaf(a3,a3,a4*a4))));
        float sb = fmaf(b0,b0,fmaf(b1,b1,fmaf(b2,b2,fmaf(b3,b3,b4*b4))));
        Rp[jp*3+0] = make_float4(a0*LOG2E, b0*LOG2E, a1*LOG2E, b1*LOG2E);
        Rp[jp*3+1] = make_float4(a2*LOG2E, b2*LOG2E, a3*LOG2E, b3*LOG2E);
        Rp[jp*3+2] = make_float4(a4*LOG2E, b4*LOG2E,
                                 sa*NHALF_LOG2E, sb*NHALF_LOG2E);
    }
    __syncthreads();

    // Per-thread rows iA, iB.
    float a0 = ref[(size_t)iA*DD+0], a1 = ref[(size_t)iA*DD+1];
    float a2 = ref[(size_t)iA*DD+2], a3 = ref[(size_t)iA*DD+3];
    float a4 = ref[(size_t)iA*DD+4];
    float b0 = ref[(size_t)iB*DD+0], b1 = ref[(size_t)iB*DD+1];
    float b2 = ref[(size_t)iB*DD+2], b3 = ref[(size_t)iB*DD+3];
    float b4 = ref[(size_t)iB*DD+4];
    const float sqA = fmaf(a0,a0,fmaf(a1,a1,fmaf(a2,a2,fmaf(a3,a3,a4*a4))));
    const float sqB = fmaf(b0,b0,fmaf(b1,b1,fmaf(b2,b2,fmaf(b3,b3,b4*b4))));

    const unsigned long long rA[DD] = {
        bcast2(a0), bcast2(a1), bcast2(a2), bcast2(a3), bcast2(a4) };
    const unsigned long long rB[DD] = {
        bcast2(b0), bcast2(b1), bcast2(b2), bcast2(b3), bcast2(b4) };
    const unsigned long long sqA2 = bcast2(sqA * NHALF_LOG2E);
    const unsigned long long sqB2 = bcast2(sqB * NHALF_LOG2E);

    unsigned long long accA[8], accB[8];   // 8 packed ch-pairs per i-row
    #pragma unroll
    for (int k = 0; k < 8; k++) { accA[k] = 0ull; accB[k] = 0ull; }

    #pragma unroll 2
    for (int jp = 0; jp < JP; jp++) {
        const float4 p0 = Rp[jp*3+0];
        const float4 p1 = Rp[jp*3+1];
        const float4 p2 = Rp[jp*3+2];
        const unsigned long long* q0 = (const unsigned long long*)&p0;
        const unsigned long long* q1 = (const unsigned long long*)&p1;
        const unsigned long long* q2 = (const unsigned long long*)&p2;

        // Two independent packed exponent-arg chains (rows iA, iB).
        unsigned long long argA = add2(sqA2, q2[1]);
        unsigned long long argB = add2(sqB2, q2[1]);
        ffma2(argA, rA[0], q0[0]);  ffma2(argB, rB[0], q0[0]);
        ffma2(argA, rA[1], q0[1]);  ffma2(argB, rB[1], q0[1]);
        ffma2(argA, rA[2], q1[0]);  ffma2(argB, rB[2], q1[0]);
        ffma2(argA, rA[3], q1[1]);  ffma2(argB, rB[3], q1[1]);
        ffma2(argA, rA[4], q2[0]);  ffma2(argB, rB[4], q2[0]);

        float eA0, eA1, eB0, eB1;
        asm("mov.b64 {%0, %1}, %2;" : "=f"(eA0), "=f"(eA1) : "l"(argA));
        asm("mov.b64 {%0, %1}, %2;" : "=f"(eB0), "=f"(eB1) : "l"(argB));
        const unsigned long long wA0 = bcast2(ex2_approx(eA0));
        const unsigned long long wA1 = bcast2(ex2_approx(eA1));
        const unsigned long long wB0 = bcast2(ex2_approx(eB0));
        const unsigned long long wB1 = bcast2(ex2_approx(eB1));

        // U rows 2jp and 2jp+1 (8 packed pairs each).
        const ulonglong2* ua = (const ulonglong2*)&Us[(2*jp    ) * 4];
        const ulonglong2* ub = (const ulonglong2*)&Us[(2*jp + 1) * 4];
        ulonglong2 u0 = ua[0], u1 = ua[1], u2 = ua[2], u3 = ua[3];
        ulonglong2 v0 = ub[0], v1 = ub[1], v2 = ub[2], v3 = ub[3];

        // Same acc reused 16 instrs apart (32 cyc) -> no RAW stall exposure.
        ffma2(accA[0], wA0, u0.x); ffma2(accA[1], wA0, u0.y);
        ffma2(accA[2], wA0, u1.x); ffma2(accA[3], wA0, u1.y);
        ffma2(accA[4], wA0, u2.x); ffma2(accA[5], wA0, u2.y);
        ffma2(accA[6], wA0, u3.x); ffma2(accA[7], wA0, u3.y);
        ffma2(accB[0], wB0, u0.x); ffma2(accB[1], wB0, u0.y);
        ffma2(accB[2], wB0, u1.x); ffma2(accB[3], wB0, u1.y);
        ffma2(accB[4], wB0, u2.x); ffma2(accB[5], wB0, u2.y);
        ffma2(accB[6], wB0, u3.x); ffma2(accB[7], wB0, u3.y);
        ffma2(accA[0], wA1, v0.x); ffma2(accA[1], wA1, v0.y);
        ffma2(accA[2], wA1, v1.x); ffma2(accA[3], wA1, v1.y);
        ffma2(accA[4], wA1, v2.x); ffma2(accA[5], wA1, v2.y);
        ffma2(accA[6], wA1, v3.x); ffma2(accA[7], wA1, v3.y);
        ffma2(accB[0], wB1, v0.x); ffma2(accB[1], wB1, v0.y);
        ffma2(accB[2], wB1, v1.x); ffma2(accB[3], wB1, v1.y);
        ffma2(accB[4], wB1, v2.x); ffma2(accB[5], wB1, v2.y);
        ffma2(accB[6], wB1, v3.x); ffma2(accB[7], wB1, v3.y);
    }

    ulonglong2* PA = reinterpret_cast<ulonglong2*>(&g_partial[blockIdx.y][iA][0]);
    ulonglong2* PB = reinterpret_cast<ulonglong2*>(&g_partial[blockIdx.y][iB][0]);
    #pragma unroll
    for (int k = 0; k < 4; k++) {
        PA[k] = make_ulonglong2(accA[2*k], accA[2*k+1]);
        PB[k] = make_ulonglong2(accB[2*k], accB[2*k+1]);
    }
}

__global__ void __launch_bounds__(256)
lg_reduce(const float4* __restrict__ U4, float4* __restrict__ out4) {
    const int idx = blockIdx.x * 256 + threadIdx.x;   // over N*C/4 = 32768
    const float4* base = reinterpret_cast<const float4*>(g_partial);
    float4 u = U4[idx];
    float4 s = make_float4(-u.x, -u.y, -u.z, -u.w);
    #pragma unroll
    for (int p = 0; p < SPLITS; p++) {
        float4 v = base[(size_t)p * (NN * CC / 4) + idx];
        s.x += v.x; s.y += v.y; s.z += v.z; s.w += v.w;
    }
    out4[idx] = s;
}

extern "C" void kernel_launch(void* const* d_in, const int* in_sizes, int n_in,
                              void* d_out, int out_size) {
    const float* U   = (const float*)d_in[0];   // [8192,16]
    const float* ref = (const float*)d_in[1];   // [8192,5]

    dim3 grid(NN / (2 * TI), SPLITS);           // (32, 16)
    lg_compute<<<grid, TI>>>(U, ref);
    lg_reduce<<<(NN * CC / 4) / 256, 256>>>((const float4*)U, (float4*)d_out);
}

// round 10
// speedup vs baseline: 1.9187x; 1.5018x over previous
#include <cuda_runtime.h>
#include <cuda_bf16.h>
#include <cstdint>

// LatticeGaussian: out = W@U - U, W_ij = exp(-0.5||ri-rj||^2). N=8192,C=16,D=5.
// HMMA (mma.sync bf16) path — compute_103-safe (no tcgen05).
//   MMA1: G[i,j] = log2e*(ri.rj) - 0.5*log2e*(|ri|^2+|rj|^2) via split-bf16
//         K=32 encoding (arg error ~2^-16 relative).
//   ex2 in registers; split w = Ph (bf16 trunc) + Pl (remainder).
//   MMA2: out += Ph@[Uh;Ul] + Pl@Uh  (fp32 accum in registers).
// FMHA fragment identity: MMA1 C-frag packs directly into MMA2 A-frag —
// P never touches shared memory.

#define NN 8192
#define CC 16
#define DD 5
#define SPLITS 8
#define JRANGE (NN / SPLITS)     // 1024 j per CTA
#define TJC 256                  // j per smem chunk
#define NCHUNK (JRANGE / TJC)    // 4
#define SB1P 40                  // padded B1 row (80B) -> conflict-free LDS
#define SUTP (TJC + 8)           // padded U^T row -> conflict-free LDS

#define LOG2E 1.4426950408889634f
#define SQRT_L 1.2011224087864498f   // sqrt(log2 e)

__device__ __align__(16) __nv_bfloat16 g_EA[NN][32];   // 512 KB encoded A rows
__device__ __align__(16) __nv_bfloat16 g_EB[NN][32];   // 512 KB encoded B rows
__device__ __align__(16) __nv_bfloat16 g_UT[32][NN];   // 512 KB U^T (0-15 hi, 16-31 lo)
__device__ float g_part[SPLITS][NN][CC];               // 4 MB partials

// ---------------- helpers ----------------
__device__ __forceinline__ float ex2a(float x) {
    float r; asm("ex2.approx.f32 %0, %1;" : "=f"(r) : "f"(x)); return r;
}
__device__ __forceinline__ uint32_t prmt7632(uint32_t a, uint32_t b) {
    // result = {lo16: a.hi16, hi16: b.hi16} == pack(trunc_bf16(a), trunc_bf16(b))
    uint32_t r; asm("prmt.b32 %0, %1, %2, 0x7632;" : "=r"(r) : "r"(a), "r"(b));
    return r;
}
__device__ __forceinline__ uint32_t pack_bf2(float lo, float hi) {
    uint32_t r;
    asm("cvt.rn.satfinite.bf16x2.f32 %0, %1, %2;" : "=r"(r) : "f"(hi), "f"(lo));
    return r;
}
__device__ __forceinline__ void mma16816(float* d,
                                         uint32_t a0, uint32_t a1,
                                         uint32_t a2, uint32_t a3,
                                         uint32_t b0, uint32_t b1) {
    asm volatile(
        "mma.sync.aligned.m16n8k16.row.col.f32.bf16.bf16.f32 "
        "{%0,%1,%2,%3}, {%4,%5,%6,%7}, {%8,%9}, {%0,%1,%2,%3};"
        : "+f"(d[0]), "+f"(d[1]), "+f"(d[2]), "+f"(d[3])
        : "r"(a0), "r"(a1), "r"(a2), "r"(a3), "r"(b0), "r"(b1));
}

// ---------------- prep: encoded tiles + U^T splits ----------------
__global__ void __launch_bounds__(128)
lg_prep(const float* __restrict__ U, const float* __restrict__ ref) {
    const int j = blockIdx.x * 128 + threadIdx.x;

    float r[DD], sq = 0.f;
    #pragma unroll
    for (int k = 0; k < DD; k++) {
        r[k] = ref[(size_t)j * DD + k];
        sq = fmaf(r[k], r[k], sq);
    }
    const float aL = -0.5f * LOG2E * sq;

    __nv_bfloat16 xh[DD], xl[DD];
    #pragma unroll
    for (int k = 0; k < DD; k++) {
        float x = SQRT_L * r[k];
        xh[k] = __float2bfloat16(x);
        xl[k] = __float2bfloat16(x - __bfloat162float(xh[k]));
    }
    const __nv_bfloat16 ah  = __float2bfloat16(aL);
    const __nv_bfloat16 al  = __float2bfloat16(aL - __bfloat162float(ah));
    const __nv_bfloat16 one = __float2bfloat16(1.0f);
    const __nv_bfloat16 zro = __float2bfloat16(0.0f);

    __nv_bfloat16 ea[32], eb[32];
    #pragma unroll
    for (int k = 0; k < 32; k++) { ea[k] = zro; eb[k] = zro; }
    #pragma unroll
    for (int k = 0; k < DD; k++) {
        ea[k]      = xh[k];  eb[k]      = xh[k];   // xh.xh
        ea[5 + k]  = xl[k];  eb[5 + k]  = xh[k];   // xl.xh
        ea[10 + k] = xh[k];  eb[10 + k] = xl[k];   // xh.xl
    }
    ea[15] = ah;  eb[15] = one;
    ea[16] = al;  eb[16] = one;
    ea[17] = one; eb[17] = ah;
    ea[18] = one; eb[18] = al;

    {
        const uint4* pa = reinterpret_cast<const uint4*>(ea);
        const uint4* pb = reinterpret_cast<const uint4*>(eb);
        uint4* da = reinterpret_cast<uint4*>(&g_EA[j][0]);
        uint4* db = reinterpret_cast<uint4*>(&g_EB[j][0]);
        #pragma unroll
        for (int q = 0; q < 4; q++) { da[q] = pa[q]; db[q] = pb[q]; }
    }

    #pragma unroll
    for (int c = 0; c < CC; c++) {
        float u = U[(size_t)j * CC + c];
        __nv_bfloat16 uh = __float2bfloat16(u);
        __nv_bfloat16 ul = __float2bfloat16(u - __bfloat162float(uh));
        g_UT[c][j]      = uh;
        g_UT[c + 16][j] = ul;
    }
}

// ---------------- main: HMMA x2 with register-resident P ----------------
__global__ void __launch_bounds__(256, 2)
lg_main() {
    __shared__ __nv_bfloat16 SB1[TJC][SB1P];  // encoded B rows, padded (20 KB)
    __shared__ __nv_bfloat16 SUT[32][SUTP];   // U^T chunk, padded    (16.5 KB)

    const int tid  = threadIdx.x;
    const int lane = tid & 31;
    const int w    = tid >> 5;
    const int i0   = blockIdx.x * 128 + w * 16;
    const int r4   = lane >> 2;          // 0..7
    const int c2   = (lane & 3) * 2;     // 0,2,4,6

    // A fragments for MMA1 (loop-invariant)
    uint32_t afr[2][4];
    #pragma unroll
    for (int ks = 0; ks < 2; ks++)
        #pragma unroll
        for (int q = 0; q < 4; q++) {
            int row = i0 + r4 + (q & 1) * 8;
            int col = ks * 16 + (q >> 1) * 8 + c2;
            afr[ks][q] = *reinterpret_cast<const uint32_t*>(&g_EA[row][col]);
        }

    float d[4][4];
    #pragma unroll
    for (int t = 0; t < 4; t++)
        #pragma unroll
        for (int q = 0; q < 4; q++) d[t][q] = 0.f;

    for (int cc = 0; cc < NCHUNK; cc++) {
        const int jbase = blockIdx.y * JRANGE + cc * TJC;
        // stage encoded B rows (one row per thread; 80B padded rows)
        {
            const uint4* s = reinterpret_cast<const uint4*>(&g_EB[jbase + tid][0]);
            uint4* dst = reinterpret_cast<uint4*>(&SB1[tid][0]);
            #pragma unroll
            for (int q = 0; q < 4; q++) dst[q] = s[q];
        }
        // stage U^T chunk (32 rows x 256 cols, 16B moves)
        #pragma unroll
        for (int idx = tid; idx < 1024; idx += 256) {
            int row = idx >> 5, off = idx & 31;
            *reinterpret_cast<uint4*>(&SUT[row][off * 8]) =
                *reinterpret_cast<const uint4*>(&g_UT[row][jbase + off * 8]);
        }
        __syncthreads();

        for (int jb = 0; jb < TJC / 16; jb++) {
            const int jl = jb * 16;

            // ---- MMA1: two 16x8 G tiles over K=32 ----
            float g0[4] = {0.f, 0.f, 0.f, 0.f};
            float g1[4] = {0.f, 0.f, 0.f, 0.f};
            {
                const int jr0 = jl + r4;
                const int jr1 = jl + 8 + r4;
                uint32_t b00 = *reinterpret_cast<const uint32_t*>(&SB1[jr0][c2]);
                uint32_t b01 = *reinterpret_cast<const uint32_t*>(&SB1[jr0][c2 + 8]);
                uint32_t b10 = *reinterpret_cast<const uint32_t*>(&SB1[jr0][16 + c2]);
                uint32_t b11 = *reinterpret_cast<const uint32_t*>(&SB1[jr0][16 + c2 + 8]);
                mma16816(g0, afr[0][0], afr[0][1], afr[0][2], afr[0][3], b00, b01);
                mma16816(g0, afr[1][0], afr[1][1], afr[1][2], afr[1][3], b10, b11);
                uint32_t e00 = *reinterpret_cast<const uint32_t*>(&SB1[jr1][c2]);
                uint32_t e01 = *reinterpret_cast<const uint32_t*>(&SB1[jr1][c2 + 8]);
                uint32_t e10 = *reinterpret_cast<const uint32_t*>(&SB1[jr1][16 + c2]);
                uint32_t e11 = *reinterpret_cast<const uint32_t*>(&SB1[jr1][16 + c2 + 8]);
                mma16816(g1, afr[0][0], afr[0][1], afr[0][2], afr[0][3], e00, e01);
                mma16816(g1, afr[1][0], afr[1][1], afr[1][2], afr[1][3], e10, e11);
            }

            // ---- ex2 + split into Ph (trunc) / Pl (remainder) ----
            float w00 = ex2a(g0[0]), w01 = ex2a(g0[1]);
            float w02 = ex2a(g0[2]), w03 = ex2a(g0[3]);
            float w10 = ex2a(g1[0]), w11 = ex2a(g1[1]);
            float w12 = ex2a(g1[2]), w13 = ex2a(g1[3]);
            uint32_t u00 = __float_as_uint(w00), u01 = __float_as_uint(w01);
            uint32_t u02 = __float_as_uint(w02), u03 = __float_as_uint(w03);
            uint32_t u10 = __float_as_uint(w10), u11 = __float_as_uint(w11);
            uint32_t u12 = __float_as_uint(w12), u13 = __float_as_uint(w13);
            uint32_t pa0 = prmt7632(u00, u01), pa1 = prmt7632(u02, u03);
            uint32_t pa2 = prmt7632(u10, u11), pa3 = prmt7632(u12, u13);
            uint32_t pl0 = pack_bf2(w00 - __uint_as_float(u00 & 0xFFFF0000u),
                                    w01 - __uint_as_float(u01 & 0xFFFF0000u));
            uint32_t pl1 = pack_bf2(w02 - __uint_as_float(u02 & 0xFFFF0000u),
                                    w03 - __uint_as_float(u03 & 0xFFFF0000u));
            uint32_t pl2 = pack_bf2(w10 - __uint_as_float(u10 & 0xFFFF0000u),
                                    w11 - __uint_as_float(u11 & 0xFFFF0000u));
            uint32_t pl3 = pack_bf2(w12 - __uint_as_float(u12 & 0xFFFF0000u),
                                    w13 - __uint_as_float(u13 & 0xFFFF0000u));

            // ---- U fragments (4 n-groups: Uh ch0-7, Uh ch8-15, Ul ch0-7, Ul ch8-15)
            uint32_t ub[4][2];
            #pragma unroll
            for (int t = 0; t < 4; t++) {
                ub[t][0] = *reinterpret_cast<const uint32_t*>(&SUT[t * 8 + r4][jl + c2]);
                ub[t][1] = *reinterpret_cast<const uint32_t*>(&SUT[t * 8 + r4][jl + c2 + 8]);
            }

            // ---- MMA2: Ph @ all, Pl @ Uh only ----
            mma16816(d[0], pa0, pa1, pa2, pa3, ub[0][0], ub[0][1]);
            mma16816(d[1], pa0, pa1, pa2, pa3, ub[1][0], ub[1][1]);
            mma16816(d[2], pa0, pa1, pa2, pa3, ub[2][0], ub[2][1]);
            mma16816(d[3], pa0, pa1, pa2, pa3, ub[3][0], ub[3][1]);
            mma16816(d[0], pl0, pl1, pl2, pl3, ub[0][0], ub[0][1]);
            mma16816(d[1], pl0, pl1, pl2, pl3, ub[1][0], ub[1][1]);
        }
        __syncthreads();
    }

    // fold hi/lo U halves and store partial: channels ch = t*8 + c2, +1
    #pragma unroll
    for (int t = 0; t < 2; t++) {
        int ch = t * 8 + c2;
        float2 v0 = make_float2(d[t][0] + d[t + 2][0], d[t][1] + d[t + 2][1]);
        float2 v1 = make_float2(d[t][2] + d[t + 2][2], d[t][3] + d[t + 2][3]);
        *reinterpret_cast<float2*>(&g_part[blockIdx.y][i0 + r4][ch]) = v0;
        *reinterpret_cast<float2*>(&g_part[blockIdx.y][i0 + r4 + 8][ch]) = v1;
    }
}

// ---------------- reduce ----------------
__global__ void __launch_bounds__(256)
lg_reduce(const float4* __restrict__ U4, float4* __restrict__ out4) {
    const int idx = blockIdx.x * 256 + threadIdx.x;     // over N*C/4
    const float4* base = reinterpret_cast<const float4*>(g_part);
    float4 u = U4[idx];
    float4 s = make_float4(-u.x, -u.y, -u.z, -u.w);
    #pragma unroll
    for (int p = 0; p < SPLITS; p++) {
        float4 v = base[(size_t)p * (NN * CC / 4) + idx];
        s.x += v.x; s.y += v.y; s.z += v.z; s.w += v.w;
    }
    out4[idx] = s;
}

extern "C" void kernel_launch(void* const* d_in, const int* in_sizes, int n_in,
                              void* d_out, int out_size) {
    const float* U   = (const float*)d_in[0];   // [8192,16]
    const float* ref = (const float*)d_in[1];   // [8192,5]

    lg_prep<<<NN / 128, 128>>>(U, ref);
    dim3 grid(NN / 128, SPLITS);                // (64, 8)
    lg_main<<<grid, 256>>>();
    lg_reduce<<<(NN * CC / 4) / 256, 256>>>((const float4*)U, (float4*)d_out);
}

// round 15
// speedup vs baseline: 1.9256x; 1.0036x over previous
#include <cuda_runtime.h>
#include <cuda_bf16.h>
#include <cstdint>

// LatticeGaussian: out = W@U - U, W_ij = exp(-0.5||ri-rj||^2). N=8192,C=16,D=5.
// HMMA (mma.sync bf16) path — compute_103-safe.
//   MMA1: G = log2e*(ri.rj) - 0.5*log2e*(|ri|^2+|rj|^2), split-bf16 K=32.
//   ex2 in regs; w = Ph (bf16 trunc) + Pl (remainder).
//   MMA2: out += Ph@[Uh;Ul] + Pl@Uh, separate Pl accumulators (no RAW reuse).
// FMHA fragment identity: MMA1 C-frag packs directly into MMA2 A-frag.

#define NN 8192
#define CC 16
#define DD 5
#define SPLITS 8
#define JRANGE (NN / SPLITS)     // 1024 j per CTA
#define TJC 256                  // j per smem chunk
#define NCHUNK (JRANGE / TJC)    // 4
#define SB1P 40                  // padded B1 row (80B) -> conflict-free LDS
#define SUTP (TJC + 8)           // padded U^T row -> conflict-free LDS

#define LOG2E 1.4426950408889634f
#define SQRT_L 1.2011224087864498f   // sqrt(log2 e)

__device__ __align__(16) __nv_bfloat16 g_EA[NN][32];   // 512 KB encoded A rows
__device__ __align__(16) __nv_bfloat16 g_EB[NN][32];   // 512 KB encoded B rows
__device__ __align__(16) __nv_bfloat16 g_UT[32][NN];   // 512 KB U^T (0-15 hi, 16-31 lo)
__device__ float g_part[SPLITS][NN][CC];               // 4 MB partials

// ---------------- helpers ----------------
__device__ __forceinline__ float ex2a(float x) {
    float r; asm("ex2.approx.f32 %0, %1;" : "=f"(r) : "f"(x)); return r;
}
__device__ __forceinline__ uint32_t prmt7632(uint32_t a, uint32_t b) {
    uint32_t r; asm("prmt.b32 %0, %1, %2, 0x7632;" : "=r"(r) : "r"(a), "r"(b));
    return r;
}
__device__ __forceinline__ uint32_t pack_bf2(float lo, float hi) {
    uint32_t r;
    asm("cvt.rn.satfinite.bf16x2.f32 %0, %1, %2;" : "=r"(r) : "f"(hi), "f"(lo));
    return r;
}
__device__ __forceinline__ void mma16816(float* d,
                                         uint32_t a0, uint32_t a1,
                                         uint32_t a2, uint32_t a3,
                                         uint32_t b0, uint32_t b1) {
    asm volatile(
        "mma.sync.aligned.m16n8k16.row.col.f32.bf16.bf16.f32 "
        "{%0,%1,%2,%3}, {%4,%5,%6,%7}, {%8,%9}, {%0,%1,%2,%3};"
        : "+f"(d[0]), "+f"(d[1]), "+f"(d[2]), "+f"(d[3])
        : "r"(a0), "r"(a1), "r"(a2), "r"(a3), "r"(b0), "r"(b1));
}

// ---------------- prep: encoded tiles + coalesced U^T splits ----------------
__global__ void __launch_bounds__(128)
lg_prep(const float* __restrict__ U, const float* __restrict__ ref) {
    __shared__ __nv_bfloat16 TU[32][128];   // U^T transpose staging (8 KB)

    const int tid   = threadIdx.x;
    const int jbase = blockIdx.x * 128;
    const int j     = jbase + tid;

    float r[DD], sq = 0.f;
    #pragma unroll
    for (int k = 0; k < DD; k++) {
        r[k] = ref[(size_t)j * DD + k];
        sq = fmaf(r[k], r[k], sq);
    }
    const float aL = -0.5f * LOG2E * sq;

    __nv_bfloat16 xh[DD], xl[DD];
    #pragma unroll
    for (int k = 0; k < DD; k++) {
        float x = SQRT_L * r[k];
        xh[k] = __float2bfloat16(x);
        xl[k] = __float2bfloat16(x - __bfloat162float(xh[k]));
    }
    const __nv_bfloat16 ah  = __float2bfloat16(aL);
    const __nv_bfloat16 al  = __float2bfloat16(aL - __bfloat162float(ah));
    const __nv_bfloat16 one = __float2bfloat16(1.0f);
    const __nv_bfloat16 zro = __float2bfloat16(0.0f);

    __nv_bfloat16 ea[32], eb[32];
    #pragma unroll
    for (int k = 0; k < 32; k++) { ea[k] = zro; eb[k] = zro; }
    #pragma unroll
    for (int k = 0; k < DD; k++) {
        ea[k]      = xh[k];  eb[k]      = xh[k];   // xh.xh
        ea[5 + k]  = xl[k];  eb[5 + k]  = xh[k];   // xl.xh
        ea[10 + k] = xh[k];  eb[10 + k] = xl[k];   // xh.xl
    }
    ea[15] = ah;  eb[15] = one;
    ea[16] = al;  eb[16] = one;
    ea[17] = one; eb[17] = ah;
    ea[18] = one; eb[18] = al;

    {
        const uint4* pa = reinterpret_cast<const uint4*>(ea);
        const uint4* pb = reinterpret_cast<const uint4*>(eb);
        uint4* da = reinterpret_cast<uint4*>(&g_EA[j][0]);
        uint4* db = reinterpret_cast<uint4*>(&g_EB[j][0]);
        #pragma unroll
        for (int q = 0; q < 4; q++) { da[q] = pa[q]; db[q] = pb[q]; }
    }

    // U^T splits via smem transpose
    #pragma unroll
    for (int c = 0; c < CC; c++) {
        float u = U[(size_t)j * CC + c];
        __nv_bfloat16 uh = __float2bfloat16(u);
        __nv_bfloat16 ul = __float2bfloat16(u - __bfloat162float(uh));
        TU[c][tid]      = uh;
        TU[c + 16][tid] = ul;
    }
    __syncthreads();
    // coalesced row writes: 32 rows x 16 segments x 16B (full 128 cols covered)
    #pragma unroll
    for (int idx = tid; idx < 32 * 16; idx += 128) {
        int row = idx >> 4, seg = idx & 15;
        *reinterpret_cast<uint4*>(&g_UT[row][jbase + seg * 8]) =
            *reinterpret_cast<const uint4*>(&TU[row][seg * 8]);
    }
}

// ---------------- main: HMMA x2 with register-resident P ----------------
__global__ void __launch_bounds__(256, 2)
lg_main() {
    __shared__ __nv_bfloat16 SB1[TJC][SB1P];  // encoded B rows, padded (20 KB)
    __shared__ __nv_bfloat16 SUT[32][SUTP];   // U^T chunk, padded    (16.5 KB)

    const int tid  = threadIdx.x;
    const int lane = tid & 31;
    const int w    = tid >> 5;
    const int i0   = blockIdx.x * 128 + w * 16;
    const int r4   = lane >> 2;          // 0..7
    const int c2   = (lane & 3) * 2;     // 0,2,4,6

    // A fragments for MMA1 (loop-invariant)
    uint32_t afr[2][4];
    #pragma unroll
    for (int ks = 0; ks < 2; ks++)
        #pragma unroll
        for (int q = 0; q < 4; q++) {
            int row = i0 + r4 + (q & 1) * 8;
            int col = ks * 16 + (q >> 1) * 8 + c2;
            afr[ks][q] = *reinterpret_cast<const uint32_t*>(&g_EA[row][col]);
        }

    float d[4][4];     // Ph accumulators: Uh ch0-7, Uh ch8-15, Ul ch0-7, Ul ch8-15
    float dl[2][4];    // Pl accumulators: Uh ch0-7, Uh ch8-15
    #pragma unroll
    for (int t = 0; t < 4; t++)
        #pragma unroll
        for (int q = 0; q < 4; q++) d[t][q] = 0.f;
    #pragma unroll
    for (int t = 0; t < 2; t++)
        #pragma unroll
        for (int q = 0; q < 4; q++) dl[t][q] = 0.f;

    for (int cc = 0; cc < NCHUNK; cc++) {
        const int jbase = blockIdx.y * JRANGE + cc * TJC;
        // stage encoded B rows (one row per thread; 80B padded rows)
        {
            const uint4* s = reinterpret_cast<const uint4*>(&g_EB[jbase + tid][0]);
            uint4* dst = reinterpret_cast<uint4*>(&SB1[tid][0]);
            #pragma unroll
            for (int q = 0; q < 4; q++) dst[q] = s[q];
        }
        // stage U^T chunk (32 rows x 256 cols, 16B moves)
        #pragma unroll
        for (int idx = tid; idx < 1024; idx += 256) {
            int row = idx >> 5, off = idx & 31;
            *reinterpret_cast<uint4*>(&SUT[row][off * 8]) =
                *reinterpret_cast<const uint4*>(&g_UT[row][jbase + off * 8]);
        }
        __syncthreads();

        #pragma unroll 2
        for (int jb = 0; jb < TJC / 16; jb++) {
            const int jl = jb * 16;

            // ---- MMA1: two 16x8 G tiles over K=32 ----
            float g0[4] = {0.f, 0.f, 0.f, 0.f};
            float g1[4] = {0.f, 0.f, 0.f, 0.f};
            {
                const int jr0 = jl + r4;
                const int jr1 = jl + 8 + r4;
                uint32_t b00 = *reinterpret_cast<const uint32_t*>(&SB1[jr0][c2]);
                uint32_t b01 = *reinterpret_cast<const uint32_t*>(&SB1[jr0][c2 + 8]);
                uint32_t b10 = *reinterpret_cast<const uint32_t*>(&SB1[jr0][16 + c2]);
                uint32_t b11 = *reinterpret_cast<const uint32_t*>(&SB1[jr0][16 + c2 + 8]);
                mma16816(g0, afr[0][0], afr[0][1], afr[0][2], afr[0][3], b00, b01);
                mma16816(g0, afr[1][0], afr[1][1], afr[1][2], afr[1][3], b10, b11);
                uint32_t e00 = *reinterpret_cast<const uint32_t*>(&SB1[jr1][c2]);
                uint32_t e01 = *reinterpret_cast<const uint32_t*>(&SB1[jr1][c2 + 8]);
                uint32_t e10 = *reinterpret_cast<const uint32_t*>(&SB1[jr1][16 + c2]);
                uint32_t e11 = *reinterpret_cast<const uint32_t*>(&SB1[jr1][16 + c2 + 8]);
                mma16816(g1, afr[0][0], afr[0][1], afr[0][2], afr[0][3], e00, e01);
                mma16816(g1, afr[1][0], afr[1][1], afr[1][2], afr[1][3], e10, e11);
            }

            // ---- ex2 + split into Ph (trunc) / Pl (remainder) ----
            float w00 = ex2a(g0[0]), w01 = ex2a(g0[1]);
            float w02 = ex2a(g0[2]), w03 = ex2a(g0[3]);
            float w10 = ex2a(g1[0]), w11 = ex2a(g1[1]);
            float w12 = ex2a(g1[2]), w13 = ex2a(g1[3]);
            uint32_t u00 = __float_as_uint(w00), u01 = __float_as_uint(w01);
            uint32_t u02 = __float_as_uint(w02), u03 = __float_as_uint(w03);
            uint32_t u10 = __float_as_uint(w10), u11 = __float_as_uint(w11);
            uint32_t u12 = __float_as_uint(w12), u13 = __float_as_uint(w13);
            uint32_t pa0 = prmt7632(u00, u01), pa1 = prmt7632(u02, u03);
            uint32_t pa2 = prmt7632(u10, u11), pa3 = prmt7632(u12, u13);
            uint32_t pl0 = pack_bf2(w00 - __uint_as_float(u00 & 0xFFFF0000u),
                                    w01 - __uint_as_float(u01 & 0xFFFF0000u));
            uint32_t pl1 = pack_bf2(w02 - __uint_as_float(u02 & 0xFFFF0000u),
                                    w03 - __uint_as_float(u03 & 0xFFFF0000u));
            uint32_t pl2 = pack_bf2(w10 - __uint_as_float(u10 & 0xFFFF0000u),
                                    w11 - __uint_as_float(u11 & 0xFFFF0000u));
            uint32_t pl3 = pack_bf2(w12 - __uint_as_float(u12 & 0xFFFF0000u),
                                    w13 - __uint_as_float(u13 & 0xFFFF0000u));

            // ---- U fragments ----
            uint32_t ub[4][2];
            #pragma unroll
            for (int t = 0; t < 4; t++) {
                ub[t][0] = *reinterpret_cast<const uint32_t*>(&SUT[t * 8 + r4][jl + c2]);
                ub[t][1] = *reinterpret_cast<const uint32_t*>(&SUT[t * 8 + r4][jl + c2 + 8]);
            }

            // ---- MMA2: each accumulator touched exactly once per iteration ----
            mma16816(d[0],  pa0, pa1, pa2, pa3, ub[0][0], ub[0][1]);
            mma16816(d[1],  pa0, pa1, pa2, pa3, ub[1][0], ub[1][1]);
            mma16816(d[2],  pa0, pa1, pa2, pa3, ub[2][0], ub[2][1]);
            mma16816(d[3],  pa0, pa1, pa2, pa3, ub[3][0], ub[3][1]);
            mma16816(dl[0], pl0, pl1, pl2, pl3, ub[0][0], ub[0][1]);
            mma16816(dl[1], pl0, pl1, pl2, pl3, ub[1][0], ub[1][1]);
        }
        __syncthreads();
    }

    // fold Ph-hi + Ph-lo + Pl contributions; channels ch = t*8 + c2, +1
    #pragma unroll
    for (int t = 0; t < 2; t++) {
        int ch = t * 8 + c2;
        float2 v0 = make_float2(d[t][0] + d[t + 2][0] + dl[t][0],
                                d[t][1] + d[t + 2][1] + dl[t][1]);
        float2 v1 = make_float2(d[t][2] + d[t + 2][2] + dl[t][2],
                                d[t][3] + d[t + 2][3] + dl[t][3]);
        *reinterpret_cast<float2*>(&g_part[blockIdx.y][i0 + r4][ch]) = v0;
        *reinterpret_cast<float2*>(&g_part[blockIdx.y][i0 + r4 + 8][ch]) = v1;
    }
}

// ---------------- reduce ----------------
__global__ void __launch_bounds__(256)
lg_reduce(const float4* __restrict__ U4, float4* __restrict__ out4) {
    const int idx = blockIdx.x * 256 + threadIdx.x;     // over N*C/4
    const float4* base = reinterpret_cast<const float4*>(g_part);
    float4 u = U4[idx];
    float4 s = make_float4(-u.x, -u.y, -u.z, -u.w);
    #pragma unroll
    for (int p = 0; p < SPLITS; p++) {
        float4 v = base[(size_t)p * (NN * CC / 4) + idx];
        s.x += v.x; s.y += v.y; s.z += v.z; s.w += v.w;
    }
    out4[idx] = s;
}

extern "C" void kernel_launch(void* const* d_in, const int* in_sizes, int n_in,
                              void* d_out, int out_size) {
    const float* U   = (const float*)d_in[0];   // [8192,16]
    const float* ref = (const float*)d_in[1];   // [8192,5]

    lg_prep<<<NN / 128, 128>>>(U, ref);
    dim3 grid(NN / 128, SPLITS);                // (64, 8)
    lg_main<<<grid, 256>>>();
    lg_reduce<<<(NN * CC / 4) / 256, 256>>>((const float4*)U, (float4*)d_out);
}

// round 17
// speedup vs baseline: 2.3606x; 1.2259x over previous
#include <cuda_runtime.h>
#include <cuda_fp16.h>
#include <cstdint>

// LatticeGaussian: out = W@U - U, W_ij = exp(-0.5||ri-rj||^2). N=8192,C=16,D=5.
// HMMA fp16 path (mma.sync m16n8k16 f32.f16) — compute_103-safe.
//   MMA1: G = log2e*(ri.rj) - 0.5*log2e*(|ri|^2+|rj|^2), split-fp16 K=32
//         (fp16 splits -> arg error ~2^-20).
//   ex2 in regs; P = fp16(w) single, unbiased rn (per-term err 2^-11).
//   MMA2: out += P@[Uh;Ul]  (U split in fp16, 4 MMAs; no Pl pass).
// 8 HMMA per 16x16 j-block (was 10 in bf16-split version) — targets the
// fallback-HMMA throughput bound identified in R15.

#define NN 8192
#define CC 16
#define DD 5
#define SPLITS 8
#define JRANGE (NN / SPLITS)     // 1024 j per CTA
#define TJC 256                  // j per smem chunk
#define NCHUNK (JRANGE / TJC)    // 4
#define SB1P 40                  // padded B1 row (80B) -> conflict-free LDS
#define SUTP (TJC + 8)           // padded U^T row -> conflict-free LDS

#define LOG2E 1.4426950408889634f
#define SQRT_L 1.2011224087864498f   // sqrt(log2 e)

__device__ __align__(16) __half g_EA[NN][32];   // 512 KB encoded A rows
__device__ __align__(16) __half g_EB[NN][32];   // 512 KB encoded B rows
__device__ __align__(16) __half g_UT[32][NN];   // 512 KB U^T (0-15 hi, 16-31 lo)
__device__ float g_part[SPLITS][NN][CC];        // 4 MB partials

// ---------------- helpers ----------------
__device__ __forceinline__ float ex2a(float x) {
    float r; asm("ex2.approx.f32 %0, %1;" : "=f"(r) : "f"(x)); return r;
}
__device__ __forceinline__ uint32_t pack_h2(float lo, float hi) {
    // low half <- lo, high half <- hi (first PTX operand lands in high half)
    uint32_t r;
    asm("cvt.rn.f16x2.f32 %0, %1, %2;" : "=r"(r) : "f"(hi), "f"(lo));
    return r;
}
__device__ __forceinline__ void mma16816(float* d,
                                         uint32_t a0, uint32_t a1,
                                         uint32_t a2, uint32_t a3,
                                         uint32_t b0, uint32_t b1) {
    asm volatile(
        "mma.sync.aligned.m16n8k16.row.col.f32.f16.f16.f32 "
        "{%0,%1,%2,%3}, {%4,%5,%6,%7}, {%8,%9}, {%0,%1,%2,%3};"
        : "+f"(d[0]), "+f"(d[1]), "+f"(d[2]), "+f"(d[3])
        : "r"(a0), "r"(a1), "r"(a2), "r"(a3), "r"(b0), "r"(b1));
}

// ---------------- prep: encoded tiles + coalesced U^T splits ----------------
__global__ void __launch_bounds__(128)
lg_prep(const float* __restrict__ U, const float* __restrict__ ref) {
    __shared__ __half TU[32][128];   // U^T transpose staging (8 KB)

    const int tid   = threadIdx.x;
    const int jbase = blockIdx.x * 128;
    const int j     = jbase + tid;

    float r[DD], sq = 0.f;
    #pragma unroll
    for (int k = 0; k < DD; k++) {
        r[k] = ref[(size_t)j * DD + k];
        sq = fmaf(r[k], r[k], sq);
    }
    const float aL = -0.5f * LOG2E * sq;

    __half xh[DD], xl[DD];
    #pragma unroll
    for (int k = 0; k < DD; k++) {
        float x = SQRT_L * r[k];
        xh[k] = __float2half_rn(x);
        xl[k] = __float2half_rn(x - __half2float(xh[k]));
    }
    const __half ah  = __float2half_rn(aL);
    const __half al  = __float2half_rn(aL - __half2float(ah));
    const __half one = __float2half_rn(1.0f);
    const __half zro = __float2half_rn(0.0f);

    __half ea[32], eb[32];
    #pragma unroll
    for (int k = 0; k < 32; k++) { ea[k] = zro; eb[k] = zro; }
    #pragma unroll
    for (int k = 0; k < DD; k++) {
        ea[k]      = xh[k];  eb[k]      = xh[k];   // xh.xh
        ea[5 + k]  = xl[k];  eb[5 + k]  = xh[k];   // xl.xh
        ea[10 + k] = xh[k];  eb[10 + k] = xl[k];   // xh.xl
    }
    ea[15] = ah;  eb[15] = one;
    ea[16] = al;  eb[16] = one;
    ea[17] = one; eb[17] = ah;
    ea[18] = one; eb[18] = al;

    {
        const uint4* pa = reinterpret_cast<const uint4*>(ea);
        const uint4* pb = reinterpret_cast<const uint4*>(eb);
        uint4* da = reinterpret_cast<uint4*>(&g_EA[j][0]);
        uint4* db = reinterpret_cast<uint4*>(&g_EB[j][0]);
        #pragma unroll
        for (int q = 0; q < 4; q++) { da[q] = pa[q]; db[q] = pb[q]; }
    }

    // U^T splits via smem transpose
    #pragma unroll
    for (int c = 0; c < CC; c++) {
        float u = U[(size_t)j * CC + c];
        __half uh = __float2half_rn(u);
        __half ul = __float2half_rn(u - __half2float(uh));
        TU[c][tid]      = uh;
        TU[c + 16][tid] = ul;
    }
    __syncthreads();
    // coalesced row writes: 32 rows x 16 segments x 16B (full 128 cols)
    #pragma unroll
    for (int idx = tid; idx < 32 * 16; idx += 128) {
        int row = idx >> 4, seg = idx & 15;
        *reinterpret_cast<uint4*>(&g_UT[row][jbase + seg * 8]) =
            *reinterpret_cast<const uint4*>(&TU[row][seg * 8]);
    }
}

// ---------------- main: HMMA x2 with register-resident P ----------------
__global__ void __launch_bounds__(256, 2)
lg_main() {
    __shared__ __half SB1[TJC][SB1P];  // encoded B rows, padded (20 KB)
    __shared__ __half SUT[32][SUTP];   // U^T chunk, padded    (16.5 KB)

    const int tid  = threadIdx.x;
    const int lane = tid & 31;
    const int w    = tid >> 5;
    const int i0   = blockIdx.x * 128 + w * 16;
    const int r4   = lane >> 2;          // 0..7
    const int c2   = (lane & 3) * 2;     // 0,2,4,6

    // A fragments for MMA1 (loop-invariant)
    uint32_t afr[2][4];
    #pragma unroll
    for (int ks = 0; ks < 2; ks++)
        #pragma unroll
        for (int q = 0; q < 4; q++) {
            int row = i0 + r4 + (q & 1) * 8;
            int col = ks * 16 + (q >> 1) * 8 + c2;
            afr[ks][q] = *reinterpret_cast<const uint32_t*>(&g_EA[row][col]);
        }

    float d[4][4];     // accumulators: Uh ch0-7, Uh ch8-15, Ul ch0-7, Ul ch8-15
    #pragma unroll
    for (int t = 0; t < 4; t++)
        #pragma unroll
        for (int q = 0; q < 4; q++) d[t][q] = 0.f;

    for (int cc = 0; cc < NCHUNK; cc++) {
        const int jbase = blockIdx.y * JRANGE + cc * TJC;
        // stage encoded B rows (one row per thread; 80B padded rows)
        {
            const uint4* s = reinterpret_cast<const uint4*>(&g_EB[jbase + tid][0]);
            uint4* dst = reinterpret_cast<uint4*>(&SB1[tid][0]);
            #pragma unroll
            for (int q = 0; q < 4; q++) dst[q] = s[q];
        }
        // stage U^T chunk (32 rows x 256 cols, 16B moves)
        #pragma unroll
        for (int idx = tid; idx < 1024; idx += 256) {
            int row = idx >> 5, off = idx & 31;
            *reinterpret_cast<uint4*>(&SUT[row][off * 8]) =
                *reinterpret_cast<const uint4*>(&g_UT[row][jbase + off * 8]);
        }
        __syncthreads();

        #pragma unroll 2
        for (int jb = 0; jb < TJC / 16; jb++) {
            const int jl = jb * 16;

            // ---- MMA1: two 16x8 G tiles over K=32 ----
            float g0[4] = {0.f, 0.f, 0.f, 0.f};
            float g1[4] = {0.f, 0.f, 0.f, 0.f};
            {
                const int jr0 = jl + r4;
                const int jr1 = jl + 8 + r4;
                uint32_t b00 = *reinterpret_cast<const uint32_t*>(&SB1[jr0][c2]);
                uint32_t b01 = *reinterpret_cast<const uint32_t*>(&SB1[jr0][c2 + 8]);
                uint32_t b10 = *reinterpret_cast<const uint32_t*>(&SB1[jr0][16 + c2]);
                uint32_t b11 = *reinterpret_cast<const uint32_t*>(&SB1[jr0][16 + c2 + 8]);
                mma16816(g0, afr[0][0], afr[0][1], afr[0][2], afr[0][3], b00, b01);
                mma16816(g0, afr[1][0], afr[1][1], afr[1][2], afr[1][3], b10, b11);
                uint32_t e00 = *reinterpret_cast<const uint32_t*>(&SB1[jr1][c2]);
                uint32_t e01 = *reinterpret_cast<const uint32_t*>(&SB1[jr1][c2 + 8]);
                uint32_t e10 = *reinterpret_cast<const uint32_t*>(&SB1[jr1][16 + c2]);
                uint32_t e11 = *reinterpret_cast<const uint32_t*>(&SB1[jr1][16 + c2 + 8]);
                mma16816(g1, afr[0][0], afr[0][1], afr[0][2], afr[0][3], e00, e01);
                mma16816(g1, afr[1][0], afr[1][1], afr[1][2], afr[1][3], e10, e11);
            }

            // ---- ex2 + single fp16 P (unbiased rn rounding) ----
            float w00 = ex2a(g0[0]), w01 = ex2a(g0[1]);
            float w02 = ex2a(g0[2]), w03 = ex2a(g0[3]);
            float w10 = ex2a(g1[0]), w11 = ex2a(g1[1]);
            float w12 = ex2a(g1[2]), w13 = ex2a(g1[3]);
            uint32_t pa0 = pack_h2(w00, w01);
            uint32_t pa1 = pack_h2(w02, w03);
            uint32_t pa2 = pack_h2(w10, w11);
            uint32_t pa3 = pack_h2(w12, w13);

            // ---- U fragments (Uh ch0-7, Uh ch8-15, Ul ch0-7, Ul ch8-15) ----
            uint32_t ub[4][2];
            #pragma unroll
            for (int t = 0; t < 4; t++) {
                ub[t][0] = *reinterpret_cast<const uint32_t*>(&SUT[t * 8 + r4][jl + c2]);
                ub[t][1] = *reinterpret_cast<const uint32_t*>(&SUT[t * 8 + r4][jl + c2 + 8]);
            }

            // ---- MMA2: P @ [Uh;Ul], 4 ops ----
            mma16816(d[0], pa0, pa1, pa2, pa3, ub[0][0], ub[0][1]);
            mma16816(d[1], pa0, pa1, pa2, pa3, ub[1][0], ub[1][1]);
            mma16816(d[2], pa0, pa1, pa2, pa3, ub[2][0], ub[2][1]);
            mma16816(d[3], pa0, pa1, pa2, pa3, ub[3][0], ub[3][1]);
        }
        __syncthreads();
    }

    // fold Uh + Ul halves; channels ch = t*8 + c2, +1
    #pragma unroll
    for (int t = 0; t < 2; t++) {
        int ch = t * 8 + c2;
        float2 v0 = make_float2(d[t][0] + d[t + 2][0], d[t][1] + d[t + 2][1]);
        float2 v1 = make_float2(d[t][2] + d[t + 2][2], d[t][3] + d[t + 2][3]);
        *reinterpret_cast<float2*>(&g_part[blockIdx.y][i0 + r4][ch]) = v0;
        *reinterpret_cast<float2*>(&g_part[blockIdx.y][i0 + r4 + 8][ch]) = v1;
    }
}

// ---------------- reduce ----------------
__global__ void __launch_bounds__(256)
lg_reduce(const float4* __restrict__ U4, float4* __restrict__ out4) {
    const int idx = blockIdx.x * 256 + threadIdx.x;     // over N*C/4
    const float4* base = reinterpret_cast<const float4*>(g_part);
    float4 u = U4[idx];
    float4 s = make_float4(-u.x, -u.y, -u.z, -u.w);
    #pragma unroll
    for (int p = 0; p < SPLITS; p++) {
        float4 v = base[(size_t)p * (NN * CC / 4) + idx];
        s.x += v.x; s.y += v.y; s.z += v.z; s.w += v.w;
    }
    out4[idx] = s;
}

extern "C" void kernel_launch(void* const* d_in, const int* in_sizes, int n_in,
                              void* d_out, int out_size) {
    const float* U   = (const float*)d_in[0];   // [8192,16]
    const float* ref = (const float*)d_in[1];   // [8192,5]

    lg_prep<<<NN / 128, 128>>>(U, ref);
    dim3 grid(NN / 128, SPLITS);                // (64, 8)
    lg_main<<<grid, 256>>>();
    lg_reduce<<<(NN * CC / 4) / 256, 256>>>((const float4*)U, (float4*)d_out);
}